// round 2
// baseline (speedup 1.0000x reference)
#include <cuda_runtime.h>
#include <cuda_bf16.h>
#include <cstdint>

#define N_NODES 50000
#define N_EDGES 800000
#define FEAT_IN 128
#define HID_ALL 256   // HEADS*HID = 4*64

// ---------------- scratch (static device globals; no allocation) ----------------
__device__ int   d_cnt[N_NODES];
__device__ int   d_rowptr[N_NODES + 1];
__device__ int   d_cursor[N_NODES];
__device__ int   d_srcsorted[N_EDGES];
__device__ __align__(16) float d_hs[(size_t)N_NODES * HID_ALL];
__device__ __align__(16) float d_hd[(size_t)N_NODES * HID_ALL];
__device__ __align__(16) float d_hs2[N_NODES * 2];
__device__ __align__(16) float d_hd2[N_NODES * 2];

// ---------------- f32x2 helpers (Blackwell packed fp32 FMA) ----------------
__device__ __forceinline__ void ffma2(unsigned long long& d, unsigned long long a, unsigned long long b) {
    asm("fma.rn.f32x2 %0, %1, %2, %0;" : "+l"(d) : "l"(a), "l"(b));
}
__device__ __forceinline__ unsigned long long pack2(float lo, float hi) {
    unsigned long long r;
    asm("mov.b64 %0, {%1, %2};" : "=l"(r) : "r"(__float_as_uint(lo)), "r"(__float_as_uint(hi)));
    return r;
}
__device__ __forceinline__ void unpack2(unsigned long long v, float& lo, float& hi) {
    unsigned int l, h;
    asm("mov.b64 {%0, %1}, %2;" : "=r"(l), "=r"(h) : "l"(v));
    lo = __uint_as_float(l);
    hi = __uint_as_float(h);
}

// ---------------- CSR build ----------------
__global__ void zero_cnt_kernel() {
    int i = blockIdx.x * blockDim.x + threadIdx.x;
    if (i < N_NODES) d_cnt[i] = 0;
}

__global__ void hist_kernel(const int* __restrict__ dst) {
    int i = blockIdx.x * blockDim.x + threadIdx.x;
    if (i < N_EDGES) atomicAdd(&d_cnt[dst[i]], 1);
}

// single-block exclusive scan over d_cnt -> d_rowptr, d_cursor
__global__ void scan_kernel() {
    __shared__ int wsum[32];
    __shared__ int sh_tot;
    int tid = threadIdx.x, lane = tid & 31, wid = tid >> 5;
    int carry = 0;
    for (int base = 0; base < N_NODES; base += 1024) {
        int i = base + tid;
        int v = (i < N_NODES) ? d_cnt[i] : 0;
        int incl = v;
#pragma unroll
        for (int o = 1; o < 32; o <<= 1) {
            int t = __shfl_up_sync(0xffffffffu, incl, o);
            if (lane >= o) incl += t;
        }
        if (lane == 31) wsum[wid] = incl;
        __syncthreads();
        if (wid == 0) {
            int s = wsum[lane];
            int si = s;
#pragma unroll
            for (int o = 1; o < 32; o <<= 1) {
                int t = __shfl_up_sync(0xffffffffu, si, o);
                if (lane >= o) si += t;
            }
            wsum[lane] = si - s;  // warp-exclusive offsets of warp sums
        }
        __syncthreads();
        int excl = carry + wsum[wid] + incl - v;
        if (i < N_NODES) {
            d_rowptr[i] = excl;
            d_cursor[i] = excl;
        }
        // BLOCK TOTAL ONLY (fix: previously included carry -> runaway rowptr
        // -> OOB scatter -> wild gathers -> err717)
        if (tid == 1023) sh_tot = wsum[31] + incl;
        __syncthreads();
        carry += sh_tot;
    }
    if (tid == 0) d_rowptr[N_NODES] = carry;
}

__global__ void scatter_kernel(const int* __restrict__ src, const int* __restrict__ dst) {
    int i = blockIdx.x * blockDim.x + threadIdx.x;
    if (i < N_EDGES) {
        int pos = atomicAdd(&d_cursor[dst[i]], 1);
        d_srcsorted[pos] = src[i];
    }
}

// ---------------- GEMM1: [N,128] @ [128,512] -> d_hs (cols 0..255), d_hd (256..511) ----------------
// BM=128, BN=64, BK=16, 256 threads; thread tile 8(M) x 4(N) held as M-pairs for f32x2.
#define BM 128
#define BN 64
#define BK 16
#define APITCH (BM + 4)  // 132

__global__ void __launch_bounds__(256) gemm1_kernel(
    const float* __restrict__ feat,
    const float* __restrict__ W1s, const float* __restrict__ b1s,
    const float* __restrict__ W1d, const float* __restrict__ b1d)
{
    __shared__ __align__(16) float As[BK][APITCH];  // A transposed: [k][m], m contiguous
    __shared__ __align__(16) float Bs[BK][BN];

    int tid = threadIdx.x;
    int tx = tid & 15;   // n direction (4 cols each)
    int ty = tid >> 4;   // m direction (8 rows each)
    int mblk = blockIdx.x * BM;
    int n0 = blockIdx.y * BN;

    const float* Wp;
    const float* bp;
    float* outp;
    int coff;
    if (n0 < HID_ALL) { Wp = W1s; bp = b1s; outp = d_hs; coff = n0; }
    else              { Wp = W1d; bp = b1d; outp = d_hd; coff = n0 - HID_ALL; }

    // A-load mapping: 4 consecutive threads cover one row's 16 k-values
    int a_k4 = tid & 3;   // 0..3 (float4 within BK)
    int a_m  = tid >> 2;  // 0..63 (plus +64 second pass)
    // B-load mapping
    int b_k  = tid >> 4;  // 0..15
    int b_n4 = tid & 15;  // 0..15

    unsigned long long c[4][4];
#pragma unroll
    for (int p = 0; p < 4; ++p)
#pragma unroll
        for (int j = 0; j < 4; ++j) c[p][j] = 0ULL;

    for (int kt = 0; kt < FEAT_IN; kt += BK) {
#pragma unroll
        for (int r = 0; r < 2; ++r) {
            int row = mblk + a_m + r * 64;
            float4 v = make_float4(0.f, 0.f, 0.f, 0.f);
            if (row < N_NODES)
                v = *(const float4*)&feat[(size_t)row * FEAT_IN + kt + a_k4 * 4];
            int m = a_m + r * 64;
            As[a_k4 * 4 + 0][m] = v.x;
            As[a_k4 * 4 + 1][m] = v.y;
            As[a_k4 * 4 + 2][m] = v.z;
            As[a_k4 * 4 + 3][m] = v.w;
        }
        *(float4*)&Bs[b_k][b_n4 * 4] =
            *(const float4*)&Wp[(size_t)(kt + b_k) * HID_ALL + coff + b_n4 * 4];
        __syncthreads();

#pragma unroll
        for (int kk = 0; kk < BK; ++kk) {
            ulonglong2 a01 = *(const ulonglong2*)&As[kk][ty * 8];
            ulonglong2 a23 = *(const ulonglong2*)&As[kk][ty * 8 + 4];
            float4 bv = *(const float4*)&Bs[kk][tx * 4];
            unsigned long long bb0 = pack2(bv.x, bv.x);
            unsigned long long bb1 = pack2(bv.y, bv.y);
            unsigned long long bb2 = pack2(bv.z, bv.z);
            unsigned long long bb3 = pack2(bv.w, bv.w);
            ffma2(c[0][0], a01.x, bb0); ffma2(c[1][0], a01.y, bb0);
            ffma2(c[2][0], a23.x, bb0); ffma2(c[3][0], a23.y, bb0);
            ffma2(c[0][1], a01.x, bb1); ffma2(c[1][1], a01.y, bb1);
            ffma2(c[2][1], a23.x, bb1); ffma2(c[3][1], a23.y, bb1);
            ffma2(c[0][2], a01.x, bb2); ffma2(c[1][2], a01.y, bb2);
            ffma2(c[2][2], a23.x, bb2); ffma2(c[3][2], a23.y, bb2);
            ffma2(c[0][3], a01.x, bb3); ffma2(c[1][3], a01.y, bb3);
            ffma2(c[2][3], a23.x, bb3); ffma2(c[3][3], a23.y, bb3);
        }
        __syncthreads();
    }

    int col = coff + tx * 4;
    float4 bias = *(const float4*)&bp[col];
#pragma unroll
    for (int p = 0; p < 4; ++p) {
        float lo0, hi0, lo1, hi1, lo2, hi2, lo3, hi3;
        unpack2(c[p][0], lo0, hi0);
        unpack2(c[p][1], lo1, hi1);
        unpack2(c[p][2], lo2, hi2);
        unpack2(c[p][3], lo3, hi3);
        int r0 = mblk + ty * 8 + 2 * p;
        if (r0 < N_NODES) {
            float4 w = make_float4(lo0 + bias.x, lo1 + bias.y, lo2 + bias.z, lo3 + bias.w);
            *(float4*)&outp[(size_t)r0 * HID_ALL + col] = w;
        }
        if (r0 + 1 < N_NODES) {
            float4 w = make_float4(hi0 + bias.x, hi1 + bias.y, hi2 + bias.z, hi3 + bias.w);
            *(float4*)&outp[(size_t)(r0 + 1) * HID_ALL + col] = w;
        }
    }
}

// ---------------- Layer-1 fused edge softmax+aggregate + ELU + layer-2 projection ----------------
// warp per dst node; lane owns 8 dims (head = lane/8, 8 lanes per head)
__device__ __forceinline__ float lrelu(float x) { return fmaxf(x, 0.2f * x); }

__global__ void __launch_bounds__(256) edge1_kernel(
    const float* __restrict__ attn1,
    const float* __restrict__ W2s, const float* __restrict__ b2s,
    const float* __restrict__ W2d, const float* __restrict__ b2d)
{
    __shared__ __align__(16) float sW[4][HID_ALL];  // [W2s.c0, W2s.c1, W2d.c0, W2d.c1][row]
    int tid = threadIdx.x;
    sW[0][tid] = W2s[2 * tid + 0];
    sW[1][tid] = W2s[2 * tid + 1];
    sW[2][tid] = W2d[2 * tid + 0];
    sW[3][tid] = W2d[2 * tid + 1];
    __syncthreads();

    int warp = tid >> 5, lane = tid & 31;
    int node = blockIdx.x * 8 + warp;
    if (node >= N_NODES) return;

    const float* hdp = &d_hd[(size_t)node * HID_ALL + lane * 8];
    float4 hd0 = *(const float4*)hdp;
    float4 hd1 = *(const float4*)(hdp + 4);
    float4 at0 = *(const float4*)&attn1[lane * 8];
    float4 at1 = *(const float4*)&attn1[lane * 8 + 4];

    float acc0 = 0.f, acc1 = 0.f, acc2 = 0.f, acc3 = 0.f;
    float acc4 = 0.f, acc5 = 0.f, acc6 = 0.f, acc7 = 0.f;
    float denom = 0.f;

    int e0 = d_rowptr[node], e1 = d_rowptr[node + 1];
    int s = (e0 < e1) ? d_srcsorted[e0] : 0;
    for (int e = e0; e < e1; ++e) {
        int snext = (e + 1 < e1) ? d_srcsorted[e + 1] : 0;
        const float* hp = &d_hs[(size_t)s * HID_ALL + lane * 8];
        float4 v0 = *(const float4*)hp;
        float4 v1 = *(const float4*)(hp + 4);

        float sc = 0.f;
        sc = fmaf(lrelu(v0.x + hd0.x), at0.x, sc);
        sc = fmaf(lrelu(v0.y + hd0.y), at0.y, sc);
        sc = fmaf(lrelu(v0.z + hd0.z), at0.z, sc);
        sc = fmaf(lrelu(v0.w + hd0.w), at0.w, sc);
        sc = fmaf(lrelu(v1.x + hd1.x), at1.x, sc);
        sc = fmaf(lrelu(v1.y + hd1.y), at1.y, sc);
        sc = fmaf(lrelu(v1.z + hd1.z), at1.z, sc);
        sc = fmaf(lrelu(v1.w + hd1.w), at1.w, sc);
        // reduce within 8-lane head group
        sc += __shfl_xor_sync(0xffffffffu, sc, 1, 8);
        sc += __shfl_xor_sync(0xffffffffu, sc, 2, 8);
        sc += __shfl_xor_sync(0xffffffffu, sc, 4, 8);

        float ex = __expf(sc);  // scores are small (|s| < ~2): no max-subtraction needed
        denom += ex;
        acc0 = fmaf(ex, v0.x, acc0);
        acc1 = fmaf(ex, v0.y, acc1);
        acc2 = fmaf(ex, v0.z, acc2);
        acc3 = fmaf(ex, v0.w, acc3);
        acc4 = fmaf(ex, v1.x, acc4);
        acc5 = fmaf(ex, v1.y, acc5);
        acc6 = fmaf(ex, v1.z, acc6);
        acc7 = fmaf(ex, v1.w, acc7);
        s = snext;
    }

    float inv = (denom > 0.f) ? (1.f / denom) : 0.f;
    float h[8];
    h[0] = acc0 * inv; h[1] = acc1 * inv; h[2] = acc2 * inv; h[3] = acc3 * inv;
    h[4] = acc4 * inv; h[5] = acc5 * inv; h[6] = acc6 * inv; h[7] = acc7 * inv;
#pragma unroll
    for (int j = 0; j < 8; ++j)
        h[j] = (h[j] > 0.f) ? h[j] : expm1f(h[j]);  // ELU

    // fused layer-2 projection: partials over this lane's 8 dims, full-warp reduce
    float p[4];
#pragma unroll
    for (int cdx = 0; cdx < 4; ++cdx) {
        float4 wa = *(const float4*)&sW[cdx][lane * 8];
        float4 wb = *(const float4*)&sW[cdx][lane * 8 + 4];
        p[cdx] = h[0] * wa.x + h[1] * wa.y + h[2] * wa.z + h[3] * wa.w
               + h[4] * wb.x + h[5] * wb.y + h[6] * wb.z + h[7] * wb.w;
    }
#pragma unroll
    for (int o = 16; o > 0; o >>= 1) {
        p[0] += __shfl_xor_sync(0xffffffffu, p[0], o);
        p[1] += __shfl_xor_sync(0xffffffffu, p[1], o);
        p[2] += __shfl_xor_sync(0xffffffffu, p[2], o);
        p[3] += __shfl_xor_sync(0xffffffffu, p[3], o);
    }
    if (lane == 0) {
        d_hs2[node * 2 + 0] = p[0] + b2s[0];
        d_hs2[node * 2 + 1] = p[1] + b2s[1];
        d_hd2[node * 2 + 0] = p[2] + b2d[0];
        d_hd2[node * 2 + 1] = p[3] + b2d[1];
    }
}

// ---------------- Layer-2 edge softmax+aggregate ----------------
__global__ void __launch_bounds__(256) edge2_kernel(
    const float* __restrict__ attn2, float* __restrict__ out)
{
    int tid = threadIdx.x;
    int warp = tid >> 5, lane = tid & 31;
    int node = blockIdx.x * 8 + warp;
    if (node >= N_NODES) return;

    float a0 = attn2[0], a1 = attn2[1];
    float2 hdv = *(const float2*)&d_hd2[node * 2];
    int e0 = d_rowptr[node], e1 = d_rowptr[node + 1];

    float acc0 = 0.f, acc1 = 0.f, den = 0.f;
    for (int e = e0 + lane; e < e1; e += 32) {
        int s = d_srcsorted[e];
        float2 sv = *(const float2*)&d_hs2[2 * s];
        float t0 = lrelu(sv.x + hdv.x);
        float t1 = lrelu(sv.y + hdv.y);
        float ex = __expf(fmaf(t0, a0, t1 * a1));
        den += ex;
        acc0 = fmaf(ex, sv.x, acc0);
        acc1 = fmaf(ex, sv.y, acc1);
    }
#pragma unroll
    for (int o = 16; o > 0; o >>= 1) {
        acc0 += __shfl_xor_sync(0xffffffffu, acc0, o);
        acc1 += __shfl_xor_sync(0xffffffffu, acc1, o);
        den  += __shfl_xor_sync(0xffffffffu, den, o);
    }
    if (lane == 0) {
        float inv = (den > 0.f) ? (1.f / den) : 0.f;
        out[node * 2 + 0] = acc0 * inv;
        out[node * 2 + 1] = acc1 * inv;
    }
}

// ---------------- launch ----------------
extern "C" void kernel_launch(void* const* d_in, const int* in_sizes, int n_in,
                              void* d_out, int out_size)
{
    const float* feat  = (const float*)d_in[0];
    const int*   src   = (const int*)d_in[1];
    const int*   dst   = (const int*)d_in[2];
    const float* W1s   = (const float*)d_in[3];
    const float* b1s   = (const float*)d_in[4];
    const float* W1d   = (const float*)d_in[5];
    const float* b1d   = (const float*)d_in[6];
    const float* attn1 = (const float*)d_in[7];
    const float* W2s   = (const float*)d_in[8];
    const float* b2s   = (const float*)d_in[9];
    const float* W2d   = (const float*)d_in[10];
    const float* b2d   = (const float*)d_in[11];
    const float* attn2 = (const float*)d_in[12];
    float* out = (float*)d_out;

    zero_cnt_kernel<<<(N_NODES + 255) / 256, 256>>>();
    hist_kernel<<<(N_EDGES + 255) / 256, 256>>>(dst);
    scan_kernel<<<1, 1024>>>();
    scatter_kernel<<<(N_EDGES + 255) / 256, 256>>>(src, dst);

    dim3 g1((N_NODES + BM - 1) / BM, (2 * HID_ALL) / BN);
    gemm1_kernel<<<g1, 256>>>(feat, W1s, b1s, W1d, b1d);

    edge1_kernel<<<(N_NODES + 7) / 8, 256>>>(attn1, W2s, b2s, W2d, b2d);
    edge2_kernel<<<(N_NODES + 7) / 8, 256>>>(attn2, out);
}

// round 5
// speedup vs baseline: 1.0060x; 1.0060x over previous
#include <cuda_runtime.h>
#include <cuda_bf16.h>
#include <cstdint>

#define N_NODES 50000
#define N_EDGES 800000
#define FEAT_IN 128
#define HID_ALL 256   // HEADS*HID = 4*64

// ---------------- scratch (static device globals; no allocation) ----------------
__device__ __align__(16) int   d_cnt[N_NODES];
__device__ __align__(16) int   d_rowptr[N_NODES + 1];
__device__ __align__(16) int   d_cursor[N_NODES];
__device__ __align__(16) int   d_srcsorted[N_EDGES];
__device__ __align__(16) float d_hs[(size_t)N_NODES * HID_ALL];
__device__ __align__(16) float d_hd[(size_t)N_NODES * HID_ALL];
__device__ __align__(16) float d_hs2[N_NODES * 2];
__device__ __align__(16) float d_hd2[N_NODES * 2];

// ---------------- f32x2 helpers (Blackwell packed fp32 FMA) ----------------
__device__ __forceinline__ void ffma2(unsigned long long& d, unsigned long long a, unsigned long long b) {
    asm("fma.rn.f32x2 %0, %1, %2, %0;" : "+l"(d) : "l"(a), "l"(b));
}
__device__ __forceinline__ unsigned long long pack2(float lo, float hi) {
    unsigned long long r;
    asm("mov.b64 %0, {%1, %2};" : "=l"(r) : "r"(__float_as_uint(lo)), "r"(__float_as_uint(hi)));
    return r;
}
__device__ __forceinline__ void unpack2(unsigned long long v, float& lo, float& hi) {
    unsigned int l, h;
    asm("mov.b64 {%0, %1}, %2;" : "=r"(l), "=r"(h) : "l"(v));
    lo = __uint_as_float(l);
    hi = __uint_as_float(h);
}

// ---------------- CSR build ----------------
__global__ void zero_cnt_kernel() {
    int i = blockIdx.x * blockDim.x + threadIdx.x;
    if (i < N_NODES) d_cnt[i] = 0;
}

__global__ void hist_kernel(const int* __restrict__ dst) {
    int i = blockIdx.x * blockDim.x + threadIdx.x;
    if (i < N_EDGES) atomicAdd(&d_cnt[dst[i]], 1);
}

// single-block exclusive scan over d_cnt -> d_rowptr, d_cursor
// 4 elements/thread per chunk: 13 serial chunks instead of 49.
__global__ void scan_kernel() {
    __shared__ int wsum[32];
    __shared__ int sh_tot;
    int tid = threadIdx.x, lane = tid & 31, wid = tid >> 5;
    int carry = 0;
    for (int base = 0; base < N_NODES; base += 4096) {
        int i0 = base + tid * 4;
        int v0 = 0, v1 = 0, v2 = 0, v3 = 0;
        if (i0 + 3 < N_NODES) {
            int4 v = *(const int4*)&d_cnt[i0];
            v0 = v.x; v1 = v.y; v2 = v.z; v3 = v.w;
        } else if (i0 < N_NODES) {
            v0 = d_cnt[i0];
            if (i0 + 1 < N_NODES) v1 = d_cnt[i0 + 1];
            if (i0 + 2 < N_NODES) v2 = d_cnt[i0 + 2];
        }
        int e1 = v0, e2 = v0 + v1, e3 = e2 + v2;
        int t = e3 + v3;  // thread total
        int incl = t;
#pragma unroll
        for (int o = 1; o < 32; o <<= 1) {
            int u = __shfl_up_sync(0xffffffffu, incl, o);
            if (lane >= o) incl += u;
        }
        if (lane == 31) wsum[wid] = incl;
        __syncthreads();
        if (wid == 0) {
            int s = wsum[lane];
            int si = s;
#pragma unroll
            for (int o = 1; o < 32; o <<= 1) {
                int u = __shfl_up_sync(0xffffffffu, si, o);
                if (lane >= o) si += u;
            }
            wsum[lane] = si - s;  // warp-exclusive offsets of warp sums
        }
        __syncthreads();
        int ebase = carry + wsum[wid] + incl - t;
        if (i0 + 3 < N_NODES) {
            int4 r = make_int4(ebase, ebase + e1, ebase + e2, ebase + e3);
            *(int4*)&d_rowptr[i0] = r;
            *(int4*)&d_cursor[i0] = r;
        } else if (i0 < N_NODES) {
            d_rowptr[i0] = ebase;         d_cursor[i0] = ebase;
            if (i0 + 1 < N_NODES) { d_rowptr[i0 + 1] = ebase + e1; d_cursor[i0 + 1] = ebase + e1; }
            if (i0 + 2 < N_NODES) { d_rowptr[i0 + 2] = ebase + e2; d_cursor[i0 + 2] = ebase + e2; }
        }
        // block total only (no carry!)
        if (tid == 1023) sh_tot = wsum[31] + incl;
        __syncthreads();
        carry += sh_tot;
    }
    if (tid == 0) d_rowptr[N_NODES] = carry;
}

__global__ void scatter_kernel(const int* __restrict__ src, const int* __restrict__ dst) {
    int i = blockIdx.x * blockDim.x + threadIdx.x;
    if (i < N_EDGES) {
        int pos = atomicAdd(&d_cursor[dst[i]], 1);
        d_srcsorted[pos] = src[i];
    }
}

// ---------------- GEMM1: [N,128] @ [128,512] -> d_hs (cols 0..255), d_hd (256..511) ----------------
// BM=128, BN=128, BK=16, 256 threads; thread tile 8(M) x 8(N), M-pairs for f32x2.
// Per k-step per block: LDS 16KB = 128 cyc == FFMA2 issue 128 cyc (balanced).
// kk loop unrolled 4x (not 16x): keeps loop body ~2.8KB SASS, inside the 6KB L0 I$.
#define BM 128
#define BN 128
#define BK 16
#define APITCH (BM + 4)  // 132

__global__ void __launch_bounds__(256) gemm1_kernel(
    const float* __restrict__ feat,
    const float* __restrict__ W1s, const float* __restrict__ b1s,
    const float* __restrict__ W1d, const float* __restrict__ b1d)
{
    __shared__ __align__(16) float As[BK][APITCH];  // A transposed: [k][m], m contiguous
    __shared__ __align__(16) float Bs[BK][BN];

    int tid = threadIdx.x;
    int tx = tid & 15;   // n direction (8 cols each)
    int ty = tid >> 4;   // m direction (8 rows each)
    int mblk = blockIdx.x * BM;
    int n0 = blockIdx.y * BN;

    const float* Wp;
    const float* bp;
    float* outp;
    int coff;
    if (n0 < HID_ALL) { Wp = W1s; bp = b1s; outp = d_hs; coff = n0; }
    else              { Wp = W1d; bp = b1d; outp = d_hd; coff = n0 - HID_ALL; }

    // A-load mapping: 4 consecutive threads cover one row's 16 k-values
    int a_k4 = tid & 3;   // 0..3 (float4 within BK)
    int a_m  = tid >> 2;  // 0..63 (plus +64 second pass)
    // B-load mapping: 16 threads cover one k-row's first 64 cols (two passes)
    int b_k  = tid >> 4;  // 0..15
    int b_n4 = tid & 15;  // 0..15

    unsigned long long c[4][8];
#pragma unroll
    for (int p = 0; p < 4; ++p)
#pragma unroll
        for (int j = 0; j < 8; ++j) c[p][j] = 0ULL;

    for (int kt = 0; kt < FEAT_IN; kt += BK) {
#pragma unroll
        for (int r = 0; r < 2; ++r) {
            int row = mblk + a_m + r * 64;
            float4 v = make_float4(0.f, 0.f, 0.f, 0.f);
            if (row < N_NODES)
                v = *(const float4*)&feat[(size_t)row * FEAT_IN + kt + a_k4 * 4];
            int m = a_m + r * 64;
            As[a_k4 * 4 + 0][m] = v.x;
            As[a_k4 * 4 + 1][m] = v.y;
            As[a_k4 * 4 + 2][m] = v.z;
            As[a_k4 * 4 + 3][m] = v.w;
        }
#pragma unroll
        for (int r = 0; r < 2; ++r) {
            *(float4*)&Bs[b_k][b_n4 * 4 + r * 64] =
                *(const float4*)&Wp[(size_t)(kt + b_k) * HID_ALL + coff + b_n4 * 4 + r * 64];
        }
        __syncthreads();

#pragma unroll 4
        for (int kk = 0; kk < BK; ++kk) {
            ulonglong2 a01 = *(const ulonglong2*)&As[kk][ty * 8];
            ulonglong2 a23 = *(const ulonglong2*)&As[kk][ty * 8 + 4];
            float4 bv0 = *(const float4*)&Bs[kk][tx * 8];
            float4 bv1 = *(const float4*)&Bs[kk][tx * 8 + 4];
            unsigned long long bb0 = pack2(bv0.x, bv0.x);
            unsigned long long bb1 = pack2(bv0.y, bv0.y);
            unsigned long long bb2 = pack2(bv0.z, bv0.z);
            unsigned long long bb3 = pack2(bv0.w, bv0.w);
            unsigned long long bb4 = pack2(bv1.x, bv1.x);
            unsigned long long bb5 = pack2(bv1.y, bv1.y);
            unsigned long long bb6 = pack2(bv1.z, bv1.z);
            unsigned long long bb7 = pack2(bv1.w, bv1.w);
            ffma2(c[0][0], a01.x, bb0); ffma2(c[1][0], a01.y, bb0);
            ffma2(c[2][0], a23.x, bb0); ffma2(c[3][0], a23.y, bb0);
            ffma2(c[0][1], a01.x, bb1); ffma2(c[1][1], a01.y, bb1);
            ffma2(c[2][1], a23.x, bb1); ffma2(c[3][1], a23.y, bb1);
            ffma2(c[0][2], a01.x, bb2); ffma2(c[1][2], a01.y, bb2);
            ffma2(c[2][2], a23.x, bb2); ffma2(c[3][2], a23.y, bb2);
            ffma2(c[0][3], a01.x, bb3); ffma2(c[1][3], a01.y, bb3);
            ffma2(c[2][3], a23.x, bb3); ffma2(c[3][3], a23.y, bb3);
            ffma2(c[0][4], a01.x, bb4); ffma2(c[1][4], a01.y, bb4);
            ffma2(c[2][4], a23.x, bb4); ffma2(c[3][4], a23.y, bb4);
            ffma2(c[0][5], a01.x, bb5); ffma2(c[1][5], a01.y, bb5);
            ffma2(c[2][5], a23.x, bb5); ffma2(c[3][5], a23.y, bb5);
            ffma2(c[0][6], a01.x, bb6); ffma2(c[1][6], a01.y, bb6);
            ffma2(c[2][6], a23.x, bb6); ffma2(c[3][6], a23.y, bb6);
            ffma2(c[0][7], a01.x, bb7); ffma2(c[1][7], a01.y, bb7);
            ffma2(c[2][7], a23.x, bb7); ffma2(c[3][7], a23.y, bb7);
        }
        __syncthreads();
    }

    int col = coff + tx * 8;
    float4 bias0 = *(const float4*)&bp[col];
    float4 bias1 = *(const float4*)&bp[col + 4];
#pragma unroll
    for (int p = 0; p < 4; ++p) {
        float lo[8], hi[8];
#pragma unroll
        for (int j = 0; j < 8; ++j) unpack2(c[p][j], lo[j], hi[j]);
        int r0 = mblk + ty * 8 + 2 * p;
        if (r0 < N_NODES) {
            *(float4*)&outp[(size_t)r0 * HID_ALL + col] =
                make_float4(lo[0] + bias0.x, lo[1] + bias0.y, lo[2] + bias0.z, lo[3] + bias0.w);
            *(float4*)&outp[(size_t)r0 * HID_ALL + col + 4] =
                make_float4(lo[4] + bias1.x, lo[5] + bias1.y, lo[6] + bias1.z, lo[7] + bias1.w);
        }
        if (r0 + 1 < N_NODES) {
            *(float4*)&outp[(size_t)(r0 + 1) * HID_ALL + col] =
                make_float4(hi[0] + bias0.x, hi[1] + bias0.y, hi[2] + bias0.z, hi[3] + bias0.w);
            *(float4*)&outp[(size_t)(r0 + 1) * HID_ALL + col + 4] =
                make_float4(hi[4] + bias1.x, hi[5] + bias1.y, hi[6] + bias1.z, hi[7] + bias1.w);
        }
    }
}

// ---------------- Layer-1 fused edge softmax+aggregate + ELU + layer-2 projection ----------------
// warp per dst node; lane owns 8 dims (head = lane/8, 8 lanes per head)
__device__ __forceinline__ float lrelu(float x) { return fmaxf(x, 0.2f * x); }

__global__ void __launch_bounds__(256) edge1_kernel(
    const float* __restrict__ attn1,
    const float* __restrict__ W2s, const float* __restrict__ b2s,
    const float* __restrict__ W2d, const float* __restrict__ b2d)
{
    __shared__ __align__(16) float sW[4][HID_ALL];  // [W2s.c0, W2s.c1, W2d.c0, W2d.c1][row]
    int tid = threadIdx.x;
    sW[0][tid] = W2s[2 * tid + 0];
    sW[1][tid] = W2s[2 * tid + 1];
    sW[2][tid] = W2d[2 * tid + 0];
    sW[3][tid] = W2d[2 * tid + 1];
    __syncthreads();

    int warp = tid >> 5, lane = tid & 31;
    int node = blockIdx.x * 8 + warp;
    if (node >= N_NODES) return;

    const float* hdp = &d_hd[(size_t)node * HID_ALL + lane * 8];
    float4 hd0 = *(const float4*)hdp;
    float4 hd1 = *(const float4*)(hdp + 4);
    float4 at0 = *(const float4*)&attn1[lane * 8];
    float4 at1 = *(const float4*)&attn1[lane * 8 + 4];

    float acc0 = 0.f, acc1 = 0.f, acc2 = 0.f, acc3 = 0.f;
    float acc4 = 0.f, acc5 = 0.f, acc6 = 0.f, acc7 = 0.f;
    float denom = 0.f;

    int e0 = d_rowptr[node], e1 = d_rowptr[node + 1];
    int s = (e0 < e1) ? d_srcsorted[e0] : 0;
    for (int e = e0; e < e1; ++e) {
        int snext = (e + 1 < e1) ? d_srcsorted[e + 1] : 0;
        const float* hp = &d_hs[(size_t)s * HID_ALL + lane * 8];
        float4 v0 = *(const float4*)hp;
        float4 v1 = *(const float4*)(hp + 4);

        float sc = 0.f;
        sc = fmaf(lrelu(v0.x + hd0.x), at0.x, sc);
        sc = fmaf(lrelu(v0.y + hd0.y), at0.y, sc);
        sc = fmaf(lrelu(v0.z + hd0.z), at0.z, sc);
        sc = fmaf(lrelu(v0.w + hd0.w), at0.w, sc);
        sc = fmaf(lrelu(v1.x + hd1.x), at1.x, sc);
        sc = fmaf(lrelu(v1.y + hd1.y), at1.y, sc);
        sc = fmaf(lrelu(v1.z + hd1.z), at1.z, sc);
        sc = fmaf(lrelu(v1.w + hd1.w), at1.w, sc);
        // reduce within 8-lane head group
        sc += __shfl_xor_sync(0xffffffffu, sc, 1, 8);
        sc += __shfl_xor_sync(0xffffffffu, sc, 2, 8);
        sc += __shfl_xor_sync(0xffffffffu, sc, 4, 8);

        float ex = __expf(sc);  // scores are small (|s| < ~2): no max-subtraction needed
        denom += ex;
        acc0 = fmaf(ex, v0.x, acc0);
        acc1 = fmaf(ex, v0.y, acc1);
        acc2 = fmaf(ex, v0.z, acc2);
        acc3 = fmaf(ex, v0.w, acc3);
        acc4 = fmaf(ex, v1.x, acc4);
        acc5 = fmaf(ex, v1.y, acc5);
        acc6 = fmaf(ex, v1.z, acc6);
        acc7 = fmaf(ex, v1.w, acc7);
        s = snext;
    }

    float inv = (denom > 0.f) ? (1.f / denom) : 0.f;
    float h[8];
    h[0] = acc0 * inv; h[1] = acc1 * inv; h[2] = acc2 * inv; h[3] = acc3 * inv;
    h[4] = acc4 * inv; h[5] = acc5 * inv; h[6] = acc6 * inv; h[7] = acc7 * inv;
#pragma unroll
    for (int j = 0; j < 8; ++j)
        h[j] = (h[j] > 0.f) ? h[j] : expm1f(h[j]);  // ELU

    // fused layer-2 projection: partials over this lane's 8 dims, full-warp reduce
    float p[4];
#pragma unroll
    for (int cdx = 0; cdx < 4; ++cdx) {
        float4 wa = *(const float4*)&sW[cdx][lane * 8];
        float4 wb = *(const float4*)&sW[cdx][lane * 8 + 4];
        p[cdx] = h[0] * wa.x + h[1] * wa.y + h[2] * wa.z + h[3] * wa.w
               + h[4] * wb.x + h[5] * wb.y + h[6] * wb.z + h[7] * wb.w;
    }
#pragma unroll
    for (int o = 16; o > 0; o >>= 1) {
        p[0] += __shfl_xor_sync(0xffffffffu, p[0], o);
        p[1] += __shfl_xor_sync(0xffffffffu, p[1], o);
        p[2] += __shfl_xor_sync(0xffffffffu, p[2], o);
        p[3] += __shfl_xor_sync(0xffffffffu, p[3], o);
    }
    if (lane == 0) {
        d_hs2[node * 2 + 0] = p[0] + b2s[0];
        d_hs2[node * 2 + 1] = p[1] + b2s[1];
        d_hd2[node * 2 + 0] = p[2] + b2d[0];
        d_hd2[node * 2 + 1] = p[3] + b2d[1];
    }
}

// ---------------- Layer-2 edge softmax+aggregate ----------------
__global__ void __launch_bounds__(256) edge2_kernel(
    const float* __restrict__ attn2, float* __restrict__ out)
{
    int tid = threadIdx.x;
    int warp = tid >> 5, lane = tid & 31;
    int node = blockIdx.x * 8 + warp;
    if (node >= N_NODES) return;

    float a0 = attn2[0], a1 = attn2[1];
    float2 hdv = *(const float2*)&d_hd2[node * 2];
    int e0 = d_rowptr[node], e1 = d_rowptr[node + 1];

    float acc0 = 0.f, acc1 = 0.f, den = 0.f;
    for (int e = e0 + lane; e < e1; e += 32) {
        int s = d_srcsorted[e];
        float2 sv = *(const float2*)&d_hs2[2 * s];
        float t0 = lrelu(sv.x + hdv.x);
        float t1 = lrelu(sv.y + hdv.y);
        float ex = __expf(fmaf(t0, a0, t1 * a1));
        den += ex;
        acc0 = fmaf(ex, sv.x, acc0);
        acc1 = fmaf(ex, sv.y, acc1);
    }
#pragma unroll
    for (int o = 16; o > 0; o >>= 1) {
        acc0 += __shfl_xor_sync(0xffffffffu, acc0, o);
        acc1 += __shfl_xor_sync(0xffffffffu, acc1, o);
        den  += __shfl_xor_sync(0xffffffffu, den, o);
    }
    if (lane == 0) {
        float inv = (den > 0.f) ? (1.f / den) : 0.f;
        out[node * 2 + 0] = acc0 * inv;
        out[node * 2 + 1] = acc1 * inv;
    }
}

// ---------------- launch ----------------
extern "C" void kernel_launch(void* const* d_in, const int* in_sizes, int n_in,
                              void* d_out, int out_size)
{
    const float* feat  = (const float*)d_in[0];
    const int*   src   = (const int*)d_in[1];
    const int*   dst   = (const int*)d_in[2];
    const float* W1s   = (const float*)d_in[3];
    const float* b1s   = (const float*)d_in[4];
    const float* W1d   = (const float*)d_in[5];
    const float* b1d   = (const float*)d_in[6];
    const float* attn1 = (const float*)d_in[7];
    const float* W2s   = (const float*)d_in[8];
    const float* b2s   = (const float*)d_in[9];
    const float* W2d   = (const float*)d_in[10];
    const float* b2d   = (const float*)d_in[11];
    const float* attn2 = (const float*)d_in[12];
    float* out = (float*)d_out;

    zero_cnt_kernel<<<(N_NODES + 255) / 256, 256>>>();
    hist_kernel<<<(N_EDGES + 255) / 256, 256>>>(dst);
    scan_kernel<<<1, 1024>>>();
    scatter_kernel<<<(N_EDGES + 255) / 256, 256>>>(src, dst);

    dim3 g1((N_NODES + BM - 1) / BM, (2 * HID_ALL) / BN);
    gemm1_kernel<<<g1, 256>>>(feat, W1s, b1s, W1d, b1d);

    edge1_kernel<<<(N_NODES + 7) / 8, 256>>>(attn1, W2s, b2s, W2d, b2d);
    edge2_kernel<<<(N_NODES + 7) / 8, 256>>>(attn2, out);
}

// round 6
// speedup vs baseline: 1.0697x; 1.0634x over previous
#include <cuda_runtime.h>
#include <cuda_fp16.h>
#include <cstdint>

#define N_NODES 50000
#define N_EDGES 800000
#define FEAT_IN 128
#define HID_ALL 256   // HEADS*HID = 4*64

// ---------------- scratch (static device globals; no allocation) ----------------
__device__ __align__(16) int    d_cnt[N_NODES];
__device__ __align__(16) int    d_rowptr[N_NODES + 1];
__device__ __align__(16) int    d_cursor[N_NODES];
__device__ __align__(16) int    d_srcsorted[N_EDGES];
__device__ __align__(16) __half d_hs_h[(size_t)N_NODES * HID_ALL];  // fp16: halves edge1 gather traffic
__device__ __align__(16) float  d_hd[(size_t)N_NODES * HID_ALL];
__device__ __align__(16) float  d_hs2[N_NODES * 2];
__device__ __align__(16) float  d_hd2[N_NODES * 2];

// ---------------- f32x2 helpers (Blackwell packed fp32 FMA) ----------------
__device__ __forceinline__ void ffma2(unsigned long long& d, unsigned long long a, unsigned long long b) {
    asm("fma.rn.f32x2 %0, %1, %2, %0;" : "+l"(d) : "l"(a), "l"(b));
}
__device__ __forceinline__ unsigned long long pack2(float lo, float hi) {
    unsigned long long r;
    asm("mov.b64 %0, {%1, %2};" : "=l"(r) : "r"(__float_as_uint(lo)), "r"(__float_as_uint(hi)));
    return r;
}
__device__ __forceinline__ void unpack2(unsigned long long v, float& lo, float& hi) {
    unsigned int l, h;
    asm("mov.b64 {%0, %1}, %2;" : "=r"(l), "=r"(h) : "l"(v));
    lo = __uint_as_float(l);
    hi = __uint_as_float(h);
}

// ---------------- CSR build ----------------
__global__ void zero_cnt_kernel() {
    int i = blockIdx.x * blockDim.x + threadIdx.x;
    if (i < N_NODES) d_cnt[i] = 0;
}

__global__ void hist_kernel(const int* __restrict__ dst) {
    int i = blockIdx.x * blockDim.x + threadIdx.x;
    if (i < N_EDGES) atomicAdd(&d_cnt[dst[i]], 1);
}

// single-block exclusive scan over d_cnt -> d_rowptr, d_cursor (4 elems/thread)
__global__ void scan_kernel() {
    __shared__ int wsum[32];
    __shared__ int sh_tot;
    int tid = threadIdx.x, lane = tid & 31, wid = tid >> 5;
    int carry = 0;
    for (int base = 0; base < N_NODES; base += 4096) {
        int i0 = base + tid * 4;
        int v0 = 0, v1 = 0, v2 = 0, v3 = 0;
        if (i0 + 3 < N_NODES) {
            int4 v = *(const int4*)&d_cnt[i0];
            v0 = v.x; v1 = v.y; v2 = v.z; v3 = v.w;
        } else if (i0 < N_NODES) {
            v0 = d_cnt[i0];
            if (i0 + 1 < N_NODES) v1 = d_cnt[i0 + 1];
            if (i0 + 2 < N_NODES) v2 = d_cnt[i0 + 2];
        }
        int e1 = v0, e2 = v0 + v1, e3 = e2 + v2;
        int t = e3 + v3;
        int incl = t;
#pragma unroll
        for (int o = 1; o < 32; o <<= 1) {
            int u = __shfl_up_sync(0xffffffffu, incl, o);
            if (lane >= o) incl += u;
        }
        if (lane == 31) wsum[wid] = incl;
        __syncthreads();
        if (wid == 0) {
            int s = wsum[lane];
            int si = s;
#pragma unroll
            for (int o = 1; o < 32; o <<= 1) {
                int u = __shfl_up_sync(0xffffffffu, si, o);
                if (lane >= o) si += u;
            }
            wsum[lane] = si - s;
        }
        __syncthreads();
        int ebase = carry + wsum[wid] + incl - t;
        if (i0 + 3 < N_NODES) {
            int4 r = make_int4(ebase, ebase + e1, ebase + e2, ebase + e3);
            *(int4*)&d_rowptr[i0] = r;
            *(int4*)&d_cursor[i0] = r;
        } else if (i0 < N_NODES) {
            d_rowptr[i0] = ebase;         d_cursor[i0] = ebase;
            if (i0 + 1 < N_NODES) { d_rowptr[i0 + 1] = ebase + e1; d_cursor[i0 + 1] = ebase + e1; }
            if (i0 + 2 < N_NODES) { d_rowptr[i0 + 2] = ebase + e2; d_cursor[i0 + 2] = ebase + e2; }
        }
        if (tid == 1023) sh_tot = wsum[31] + incl;  // block total only
        __syncthreads();
        carry += sh_tot;
    }
    if (tid == 0) d_rowptr[N_NODES] = carry;
}

__global__ void scatter_kernel(const int* __restrict__ src, const int* __restrict__ dst) {
    int i = blockIdx.x * blockDim.x + threadIdx.x;
    if (i < N_EDGES) {
        int pos = atomicAdd(&d_cursor[dst[i]], 1);
        d_srcsorted[pos] = src[i];
    }
}

// ---------------- GEMM1: [N,128] @ [128,512] -> d_hs_h (fp16, cols 0..255), d_hd (fp32, 256..511) ----
// BM=128, BN=128, BK=16, 256 threads, 8x8 thread tile as f32x2 M-pairs.
// Register-staged prefetch: next k-tile's gmem loads issued before current tile's compute.
#define BM 128
#define BN 128
#define BK 16
#define APITCH (BM + 4)  // 132

__global__ void __launch_bounds__(256) gemm1_kernel(
    const float* __restrict__ feat,
    const float* __restrict__ W1s, const float* __restrict__ b1s,
    const float* __restrict__ W1d, const float* __restrict__ b1d)
{
    __shared__ __align__(16) float As[BK][APITCH];  // A transposed: [k][m]
    __shared__ __align__(16) float Bs[BK][BN];

    int tid = threadIdx.x;
    int tx = tid & 15;   // n direction (8 cols each)
    int ty = tid >> 4;   // m direction (8 rows each)
    int mblk = blockIdx.x * BM;
    int n0 = blockIdx.y * BN;

    bool is_hs = (n0 < HID_ALL);
    const float* Wp = is_hs ? W1s : W1d;
    const float* bp = is_hs ? b1s : b1d;
    int coff = is_hs ? n0 : (n0 - HID_ALL);

    int a_k4 = tid & 3;   // float4 index within BK
    int a_m  = tid >> 2;  // 0..63 (+64 second pass)
    int b_k  = tid >> 4;  // 0..15
    int b_n4 = tid & 15;  // 0..15

    unsigned long long c[4][8];
#pragma unroll
    for (int p = 0; p < 4; ++p)
#pragma unroll
        for (int j = 0; j < 8; ++j) c[p][j] = 0ULL;

    int rowA0 = mblk + a_m;
    int rowA1 = mblk + a_m + 64;
    const float* wrow = &Wp[(size_t)b_k * HID_ALL + coff + b_n4 * 4];

    // --- preload k-tile 0 into registers ---
    float4 va0 = make_float4(0.f, 0.f, 0.f, 0.f), va1 = va0;
    if (rowA0 < N_NODES) va0 = *(const float4*)&feat[(size_t)rowA0 * FEAT_IN + a_k4 * 4];
    if (rowA1 < N_NODES) va1 = *(const float4*)&feat[(size_t)rowA1 * FEAT_IN + a_k4 * 4];
    float4 vb0 = *(const float4*)&wrow[0];
    float4 vb1 = *(const float4*)&wrow[64];

    for (int kt = 0; kt < FEAT_IN; kt += BK) {
        // store staged regs to smem
        int m0 = a_m;
        As[a_k4 * 4 + 0][m0] = va0.x; As[a_k4 * 4 + 1][m0] = va0.y;
        As[a_k4 * 4 + 2][m0] = va0.z; As[a_k4 * 4 + 3][m0] = va0.w;
        int m1 = a_m + 64;
        As[a_k4 * 4 + 0][m1] = va1.x; As[a_k4 * 4 + 1][m1] = va1.y;
        As[a_k4 * 4 + 2][m1] = va1.z; As[a_k4 * 4 + 3][m1] = va1.w;
        *(float4*)&Bs[b_k][b_n4 * 4]      = vb0;
        *(float4*)&Bs[b_k][b_n4 * 4 + 64] = vb1;
        __syncthreads();

        // prefetch next k-tile (overlaps with compute below)
        int ktn = kt + BK;
        if (ktn < FEAT_IN) {
            va0 = make_float4(0.f, 0.f, 0.f, 0.f); va1 = va0;
            if (rowA0 < N_NODES) va0 = *(const float4*)&feat[(size_t)rowA0 * FEAT_IN + ktn + a_k4 * 4];
            if (rowA1 < N_NODES) va1 = *(const float4*)&feat[(size_t)rowA1 * FEAT_IN + ktn + a_k4 * 4];
            vb0 = *(const float4*)&wrow[(size_t)ktn * HID_ALL];
            vb1 = *(const float4*)&wrow[(size_t)ktn * HID_ALL + 64];
        }

#pragma unroll 4
        for (int kk = 0; kk < BK; ++kk) {
            ulonglong2 a01 = *(const ulonglong2*)&As[kk][ty * 8];
            ulonglong2 a23 = *(const ulonglong2*)&As[kk][ty * 8 + 4];
            float4 bv0 = *(const float4*)&Bs[kk][tx * 8];
            float4 bv1 = *(const float4*)&Bs[kk][tx * 8 + 4];
            unsigned long long bb0 = pack2(bv0.x, bv0.x);
            unsigned long long bb1 = pack2(bv0.y, bv0.y);
            unsigned long long bb2 = pack2(bv0.z, bv0.z);
            unsigned long long bb3 = pack2(bv0.w, bv0.w);
            unsigned long long bb4 = pack2(bv1.x, bv1.x);
            unsigned long long bb5 = pack2(bv1.y, bv1.y);
            unsigned long long bb6 = pack2(bv1.z, bv1.z);
            unsigned long long bb7 = pack2(bv1.w, bv1.w);
            ffma2(c[0][0], a01.x, bb0); ffma2(c[1][0], a01.y, bb0);
            ffma2(c[2][0], a23.x, bb0); ffma2(c[3][0], a23.y, bb0);
            ffma2(c[0][1], a01.x, bb1); ffma2(c[1][1], a01.y, bb1);
            ffma2(c[2][1], a23.x, bb1); ffma2(c[3][1], a23.y, bb1);
            ffma2(c[0][2], a01.x, bb2); ffma2(c[1][2], a01.y, bb2);
            ffma2(c[2][2], a23.x, bb2); ffma2(c[3][2], a23.y, bb2);
            ffma2(c[0][3], a01.x, bb3); ffma2(c[1][3], a01.y, bb3);
            ffma2(c[2][3], a23.x, bb3); ffma2(c[3][3], a23.y, bb3);
            ffma2(c[0][4], a01.x, bb4); ffma2(c[1][4], a01.y, bb4);
            ffma2(c[2][4], a23.x, bb4); ffma2(c[3][4], a23.y, bb4);
            ffma2(c[0][5], a01.x, bb5); ffma2(c[1][5], a01.y, bb5);
            ffma2(c[2][5], a23.x, bb5); ffma2(c[3][5], a23.y, bb5);
            ffma2(c[0][6], a01.x, bb6); ffma2(c[1][6], a01.y, bb6);
            ffma2(c[2][6], a23.x, bb6); ffma2(c[3][6], a23.y, bb6);
            ffma2(c[0][7], a01.x, bb7); ffma2(c[1][7], a01.y, bb7);
            ffma2(c[2][7], a23.x, bb7); ffma2(c[3][7], a23.y, bb7);
        }
        __syncthreads();
    }

    int col = coff + tx * 8;
    float4 bias0 = *(const float4*)&bp[col];
    float4 bias1 = *(const float4*)&bp[col + 4];
#pragma unroll
    for (int p = 0; p < 4; ++p) {
        float lo[8], hi[8];
#pragma unroll
        for (int j = 0; j < 8; ++j) unpack2(c[p][j], lo[j], hi[j]);
#pragma unroll
        for (int j = 0; j < 4; ++j) {
            lo[j] += (&bias0.x)[j]; lo[j + 4] += (&bias1.x)[j];
            hi[j] += (&bias0.x)[j]; hi[j + 4] += (&bias1.x)[j];
        }
        int r0 = mblk + ty * 8 + 2 * p;
        if (is_hs) {
            if (r0 < N_NODES) {
                __half2 o0 = __floats2half2_rn(lo[0], lo[1]);
                __half2 o1 = __floats2half2_rn(lo[2], lo[3]);
                __half2 o2 = __floats2half2_rn(lo[4], lo[5]);
                __half2 o3 = __floats2half2_rn(lo[6], lo[7]);
                uint4 w = make_uint4(*(unsigned*)&o0, *(unsigned*)&o1, *(unsigned*)&o2, *(unsigned*)&o3);
                *(uint4*)&d_hs_h[(size_t)r0 * HID_ALL + col] = w;
            }
            if (r0 + 1 < N_NODES) {
                __half2 o0 = __floats2half2_rn(hi[0], hi[1]);
                __half2 o1 = __floats2half2_rn(hi[2], hi[3]);
                __half2 o2 = __floats2half2_rn(hi[4], hi[5]);
                __half2 o3 = __floats2half2_rn(hi[6], hi[7]);
                uint4 w = make_uint4(*(unsigned*)&o0, *(unsigned*)&o1, *(unsigned*)&o2, *(unsigned*)&o3);
                *(uint4*)&d_hs_h[(size_t)(r0 + 1) * HID_ALL + col] = w;
            }
        } else {
            if (r0 < N_NODES) {
                *(float4*)&d_hd[(size_t)r0 * HID_ALL + col]     = make_float4(lo[0], lo[1], lo[2], lo[3]);
                *(float4*)&d_hd[(size_t)r0 * HID_ALL + col + 4] = make_float4(lo[4], lo[5], lo[6], lo[7]);
            }
            if (r0 + 1 < N_NODES) {
                *(float4*)&d_hd[(size_t)(r0 + 1) * HID_ALL + col]     = make_float4(hi[0], hi[1], hi[2], hi[3]);
                *(float4*)&d_hd[(size_t)(r0 + 1) * HID_ALL + col + 4] = make_float4(hi[4], hi[5], hi[6], hi[7]);
            }
        }
    }
}

// ---------------- Layer-1 fused edge softmax+aggregate + ELU + layer-2 projection ----------------
// warp per dst node; lane owns 8 dims (head = lane/8). hs gathered as fp16 (16B/lane/edge).
__device__ __forceinline__ float lrelu(float x) { return fmaxf(x, 0.2f * x); }

__global__ void __launch_bounds__(256) edge1_kernel(
    const float* __restrict__ attn1,
    const float* __restrict__ W2s, const float* __restrict__ b2s,
    const float* __restrict__ W2d, const float* __restrict__ b2d)
{
    __shared__ __align__(16) float sW[4][HID_ALL];
    int tid = threadIdx.x;
    sW[0][tid] = W2s[2 * tid + 0];
    sW[1][tid] = W2s[2 * tid + 1];
    sW[2][tid] = W2d[2 * tid + 0];
    sW[3][tid] = W2d[2 * tid + 1];
    __syncthreads();

    int warp = tid >> 5, lane = tid & 31;
    int node = blockIdx.x * 8 + warp;
    if (node >= N_NODES) return;

    const float* hdp = &d_hd[(size_t)node * HID_ALL + lane * 8];
    float4 hd0 = *(const float4*)hdp;
    float4 hd1 = *(const float4*)(hdp + 4);
    float4 at0 = *(const float4*)&attn1[lane * 8];
    float4 at1 = *(const float4*)&attn1[lane * 8 + 4];

    float acc0 = 0.f, acc1 = 0.f, acc2 = 0.f, acc3 = 0.f;
    float acc4 = 0.f, acc5 = 0.f, acc6 = 0.f, acc7 = 0.f;
    float denom = 0.f;

    int e0 = d_rowptr[node], e1 = d_rowptr[node + 1];
    int s = (e0 < e1) ? d_srcsorted[e0] : 0;
    for (int e = e0; e < e1; ++e) {
        int snext = (e + 1 < e1) ? d_srcsorted[e + 1] : 0;
        uint4 raw = *(const uint4*)&d_hs_h[(size_t)s * HID_ALL + lane * 8];
        float2 f0 = __half22float2(*(__half2*)&raw.x);
        float2 f1 = __half22float2(*(__half2*)&raw.y);
        float2 f2 = __half22float2(*(__half2*)&raw.z);
        float2 f3 = __half22float2(*(__half2*)&raw.w);

        float sc = 0.f;
        sc = fmaf(lrelu(f0.x + hd0.x), at0.x, sc);
        sc = fmaf(lrelu(f0.y + hd0.y), at0.y, sc);
        sc = fmaf(lrelu(f1.x + hd0.z), at0.z, sc);
        sc = fmaf(lrelu(f1.y + hd0.w), at0.w, sc);
        sc = fmaf(lrelu(f2.x + hd1.x), at1.x, sc);
        sc = fmaf(lrelu(f2.y + hd1.y), at1.y, sc);
        sc = fmaf(lrelu(f3.x + hd1.z), at1.z, sc);
        sc = fmaf(lrelu(f3.y + hd1.w), at1.w, sc);
        // reduce within 8-lane head group
        sc += __shfl_xor_sync(0xffffffffu, sc, 1, 8);
        sc += __shfl_xor_sync(0xffffffffu, sc, 2, 8);
        sc += __shfl_xor_sync(0xffffffffu, sc, 4, 8);

        float ex = __expf(sc);  // scores are small: no max-subtraction needed
        denom += ex;
        acc0 = fmaf(ex, f0.x, acc0);
        acc1 = fmaf(ex, f0.y, acc1);
        acc2 = fmaf(ex, f1.x, acc2);
        acc3 = fmaf(ex, f1.y, acc3);
        acc4 = fmaf(ex, f2.x, acc4);
        acc5 = fmaf(ex, f2.y, acc5);
        acc6 = fmaf(ex, f3.x, acc6);
        acc7 = fmaf(ex, f3.y, acc7);
        s = snext;
    }

    float inv = (denom > 0.f) ? (1.f / denom) : 0.f;
    float h[8];
    h[0] = acc0 * inv; h[1] = acc1 * inv; h[2] = acc2 * inv; h[3] = acc3 * inv;
    h[4] = acc4 * inv; h[5] = acc5 * inv; h[6] = acc6 * inv; h[7] = acc7 * inv;
#pragma unroll
    for (int j = 0; j < 8; ++j)
        h[j] = (h[j] > 0.f) ? h[j] : expm1f(h[j]);  // ELU

    float p[4];
#pragma unroll
    for (int cdx = 0; cdx < 4; ++cdx) {
        float4 wa = *(const float4*)&sW[cdx][lane * 8];
        float4 wb = *(const float4*)&sW[cdx][lane * 8 + 4];
        p[cdx] = h[0] * wa.x + h[1] * wa.y + h[2] * wa.z + h[3] * wa.w
               + h[4] * wb.x + h[5] * wb.y + h[6] * wb.z + h[7] * wb.w;
    }
#pragma unroll
    for (int o = 16; o > 0; o >>= 1) {
        p[0] += __shfl_xor_sync(0xffffffffu, p[0], o);
        p[1] += __shfl_xor_sync(0xffffffffu, p[1], o);
        p[2] += __shfl_xor_sync(0xffffffffu, p[2], o);
        p[3] += __shfl_xor_sync(0xffffffffu, p[3], o);
    }
    if (lane == 0) {
        d_hs2[node * 2 + 0] = p[0] + b2s[0];
        d_hs2[node * 2 + 1] = p[1] + b2s[1];
        d_hd2[node * 2 + 0] = p[2] + b2d[0];
        d_hd2[node * 2 + 1] = p[3] + b2d[1];
    }
}

// ---------------- Layer-2 edge softmax+aggregate ----------------
__global__ void __launch_bounds__(256) edge2_kernel(
    const float* __restrict__ attn2, float* __restrict__ out)
{
    int tid = threadIdx.x;
    int warp = tid >> 5, lane = tid & 31;
    int node = blockIdx.x * 8 + warp;
    if (node >= N_NODES) return;

    float a0 = attn2[0], a1 = attn2[1];
    float2 hdv = *(const float2*)&d_hd2[node * 2];
    int e0 = d_rowptr[node], e1 = d_rowptr[node + 1];

    float acc0 = 0.f, acc1 = 0.f, den = 0.f;
    for (int e = e0 + lane; e < e1; e += 32) {
        int s = d_srcsorted[e];
        float2 sv = *(const float2*)&d_hs2[2 * s];
        float t0 = lrelu(sv.x + hdv.x);
        float t1 = lrelu(sv.y + hdv.y);
        float ex = __expf(fmaf(t0, a0, t1 * a1));
        den += ex;
        acc0 = fmaf(ex, sv.x, acc0);
        acc1 = fmaf(ex, sv.y, acc1);
    }
#pragma unroll
    for (int o = 16; o > 0; o >>= 1) {
        acc0 += __shfl_xor_sync(0xffffffffu, acc0, o);
        acc1 += __shfl_xor_sync(0xffffffffu, acc1, o);
        den  += __shfl_xor_sync(0xffffffffu, den, o);
    }
    if (lane == 0) {
        float inv = (den > 0.f) ? (1.f / den) : 0.f;
        out[node * 2 + 0] = acc0 * inv;
        out[node * 2 + 1] = acc1 * inv;
    }
}

// ---------------- launch ----------------
extern "C" void kernel_launch(void* const* d_in, const int* in_sizes, int n_in,
                              void* d_out, int out_size)
{
    const float* feat  = (const float*)d_in[0];
    const int*   src   = (const int*)d_in[1];
    const int*   dst   = (const int*)d_in[2];
    const float* W1s   = (const float*)d_in[3];
    const float* b1s   = (const float*)d_in[4];
    const float* W1d   = (const float*)d_in[5];
    const float* b1d   = (const float*)d_in[6];
    const float* attn1 = (const float*)d_in[7];
    const float* W2s   = (const float*)d_in[8];
    const float* b2s   = (const float*)d_in[9];
    const float* W2d   = (const float*)d_in[10];
    const float* b2d   = (const float*)d_in[11];
    const float* attn2 = (const float*)d_in[12];
    float* out = (float*)d_out;

    zero_cnt_kernel<<<(N_NODES + 255) / 256, 256>>>();
    hist_kernel<<<(N_EDGES + 255) / 256, 256>>>(dst);
    scan_kernel<<<1, 1024>>>();
    scatter_kernel<<<(N_EDGES + 255) / 256, 256>>>(src, dst);

    dim3 g1((N_NODES + BM - 1) / BM, (2 * HID_ALL) / BN);
    gemm1_kernel<<<g1, 256>>>(feat, W1s, b1s, W1d, b1d);

    edge1_kernel<<<(N_NODES + 7) / 8, 256>>>(attn1, W2s, b2s, W2d, b2d);
    edge2_kernel<<<(N_NODES + 7) / 8, 256>>>(attn2, out);
}

// round 7
// speedup vs baseline: 1.6095x; 1.5046x over previous
#include <cuda_runtime.h>
#include <cuda_fp16.h>
#include <cstdint>

#define N_NODES 50000
#define N_EDGES 800000
#define FEAT_IN 128
#define HID_ALL 256   // HEADS*HID = 4*64

// ---------------- scratch (static device globals; no allocation) ----------------
__device__ __align__(16) int    d_cnt[N_NODES];
__device__ __align__(16) int    d_rowptr[N_NODES + 1];
__device__ __align__(16) int    d_cursor[N_NODES];
__device__ __align__(16) int    d_srcsorted[N_EDGES];
__device__ __align__(16) __half d_featH[(size_t)N_NODES * FEAT_IN];   // fp16 feat for MMA
__device__ __align__(16) __half d_WH[FEAT_IN * 512];                  // W1s||W1d fp16, [k][512]
__device__ __align__(16) float  d_biasC[512];                         // b1s||b1d
__device__ __align__(16) __half d_hs_h[(size_t)N_NODES * HID_ALL];    // fp16 hs (edge1 gather)
__device__ __align__(16) float  d_hd[(size_t)N_NODES * HID_ALL];
__device__ __align__(16) float  d_hs2[N_NODES * 2];
__device__ __align__(16) float  d_hd2[N_NODES * 2];

// ---------------- MMA helpers ----------------
__device__ __forceinline__ uint32_t smem_u32(const void* p) {
    return (uint32_t)__cvta_generic_to_shared(p);
}
#define LDMATRIX_X4(r0, r1, r2, r3, addr) \
    asm volatile("ldmatrix.sync.aligned.m8n8.x4.shared.b16 {%0,%1,%2,%3}, [%4];" \
                 : "=r"(r0), "=r"(r1), "=r"(r2), "=r"(r3) : "r"(addr))
#define LDMATRIX_X4_T(r0, r1, r2, r3, addr) \
    asm volatile("ldmatrix.sync.aligned.m8n8.x4.trans.shared.b16 {%0,%1,%2,%3}, [%4];" \
                 : "=r"(r0), "=r"(r1), "=r"(r2), "=r"(r3) : "r"(addr))
#define MMA16816(c, a, b0, b1) \
    asm volatile("mma.sync.aligned.m16n8k16.row.col.f32.f16.f16.f32 " \
                 "{%0,%1,%2,%3}, {%4,%5,%6,%7}, {%8,%9}, {%0,%1,%2,%3};" \
                 : "+f"((c)[0]), "+f"((c)[1]), "+f"((c)[2]), "+f"((c)[3]) \
                 : "r"((a)[0]), "r"((a)[1]), "r"((a)[2]), "r"((a)[3]), "r"(b0), "r"(b1))

// ---------------- CSR build ----------------
__global__ void zero_cnt_kernel() {
    int i = blockIdx.x * blockDim.x + threadIdx.x;
    if (i < N_NODES) d_cnt[i] = 0;
}

__global__ void hist_kernel(const int* __restrict__ dst) {
    int i = blockIdx.x * blockDim.x + threadIdx.x;
    if (i < N_EDGES) atomicAdd(&d_cnt[dst[i]], 1);
}

__global__ void scan_kernel() {
    __shared__ int wsum[32];
    __shared__ int sh_tot;
    int tid = threadIdx.x, lane = tid & 31, wid = tid >> 5;
    int carry = 0;
    for (int base = 0; base < N_NODES; base += 4096) {
        int i0 = base + tid * 4;
        int v0 = 0, v1 = 0, v2 = 0, v3 = 0;
        if (i0 + 3 < N_NODES) {
            int4 v = *(const int4*)&d_cnt[i0];
            v0 = v.x; v1 = v.y; v2 = v.z; v3 = v.w;
        } else if (i0 < N_NODES) {
            v0 = d_cnt[i0];
            if (i0 + 1 < N_NODES) v1 = d_cnt[i0 + 1];
            if (i0 + 2 < N_NODES) v2 = d_cnt[i0 + 2];
        }
        int e1 = v0, e2 = v0 + v1, e3 = e2 + v2;
        int t = e3 + v3;
        int incl = t;
#pragma unroll
        for (int o = 1; o < 32; o <<= 1) {
            int u = __shfl_up_sync(0xffffffffu, incl, o);
            if (lane >= o) incl += u;
        }
        if (lane == 31) wsum[wid] = incl;
        __syncthreads();
        if (wid == 0) {
            int s = wsum[lane];
            int si = s;
#pragma unroll
            for (int o = 1; o < 32; o <<= 1) {
                int u = __shfl_up_sync(0xffffffffu, si, o);
                if (lane >= o) si += u;
            }
            wsum[lane] = si - s;
        }
        __syncthreads();
        int ebase = carry + wsum[wid] + incl - t;
        if (i0 + 3 < N_NODES) {
            int4 r = make_int4(ebase, ebase + e1, ebase + e2, ebase + e3);
            *(int4*)&d_rowptr[i0] = r;
            *(int4*)&d_cursor[i0] = r;
        } else if (i0 < N_NODES) {
            d_rowptr[i0] = ebase;         d_cursor[i0] = ebase;
            if (i0 + 1 < N_NODES) { d_rowptr[i0 + 1] = ebase + e1; d_cursor[i0 + 1] = ebase + e1; }
            if (i0 + 2 < N_NODES) { d_rowptr[i0 + 2] = ebase + e2; d_cursor[i0 + 2] = ebase + e2; }
        }
        if (tid == 1023) sh_tot = wsum[31] + incl;  // block total only
        __syncthreads();
        carry += sh_tot;
    }
    if (tid == 0) d_rowptr[N_NODES] = carry;
}

__global__ void scatter_kernel(const int* __restrict__ src, const int* __restrict__ dst) {
    int i = blockIdx.x * blockDim.x + threadIdx.x;
    if (i < N_EDGES) {
        int pos = atomicAdd(&d_cursor[dst[i]], 1);
        d_srcsorted[pos] = src[i];
    }
}

// ---------------- convert: feat/W/bias -> fp16 staging ----------------
#define FEATV (N_NODES * FEAT_IN / 4)  // float4 groups: 1.6M
__global__ void convert_kernel(
    const float* __restrict__ feat,
    const float* __restrict__ W1s, const float* __restrict__ W1d,
    const float* __restrict__ b1s, const float* __restrict__ b1d)
{
    int i = blockIdx.x * blockDim.x + threadIdx.x;
    if (i < FEATV) {
        float4 v = ((const float4*)feat)[i];
        __half2 h0 = __floats2half2_rn(v.x, v.y);
        __half2 h1 = __floats2half2_rn(v.z, v.w);
        ((uint2*)d_featH)[i] = make_uint2(*(unsigned*)&h0, *(unsigned*)&h1);
    } else {
        int j = i - FEATV;
        if (j < FEAT_IN * 512) {
            int k = j >> 9, n = j & 511;
            float w = (n < HID_ALL) ? W1s[k * HID_ALL + n] : W1d[k * HID_ALL + (n - HID_ALL)];
            d_WH[j] = __float2half(w);
        } else if (j < FEAT_IN * 512 + 512) {
            int n = j - FEAT_IN * 512;
            d_biasC[n] = (n < HID_ALL) ? b1s[n] : b1d[n - HID_ALL];
        }
    }
}

// ---------------- GEMM (fp16 tensor cores): [N,128] @ [128,512] ----------------
// Block 128x128, BK=64, 256 thr, 8 warps as 4(M)x2(N); warp tile 32x64.
// A: ldmatrix.x4 (row-major), B: ldmatrix.x4.trans ([k][n] -> col-major frags).
// cols 0..255 -> d_hs_h (fp16), 256..511 -> d_hd (fp32). Bias fused.
#define GBM 128
#define GBK 64
#define APAD 8
#define BPAD 8

__global__ void __launch_bounds__(256) gemm_mma_kernel()
{
    __shared__ __align__(16) __half As[GBM][GBK + APAD];   // 128 x 72 (row stride 144B)
    __shared__ __align__(16) __half Bs[GBK][GBM + BPAD];   // 64 x 136 (row stride 272B)
    __shared__ float sBias[GBM];

    int tid = threadIdx.x, lane = tid & 31, warp = tid >> 5;
    int mblk = blockIdx.x * GBM;
    int nblk = blockIdx.y * GBM;
    int wm0 = (warp >> 1) * 32;
    int wn0 = (warp & 1) * 64;

    if (tid < GBM) sBias[tid] = d_biasC[nblk + tid];

    float c[2][8][4];
#pragma unroll
    for (int mt = 0; mt < 2; ++mt)
#pragma unroll
        for (int nt = 0; nt < 8; ++nt)
#pragma unroll
            for (int q = 0; q < 4; ++q) c[mt][nt][q] = 0.f;

    int ar = tid >> 3, aco = (tid & 7) * 8;       // A: 8 thr/row, 32 rows/pass
    int br = tid >> 4, bco = (tid & 15) * 8;      // B: 16 thr/row, 16 rows/pass

    for (int kt = 0; kt < FEAT_IN; kt += GBK) {
#pragma unroll
        for (int p = 0; p < 4; ++p) {
            int row = mblk + ar + p * 32;
            uint4 v = make_uint4(0, 0, 0, 0);
            if (row < N_NODES) v = *(const uint4*)&d_featH[(size_t)row * FEAT_IN + kt + aco];
            *(uint4*)&As[ar + p * 32][aco] = v;
        }
#pragma unroll
        for (int p = 0; p < 4; ++p) {
            uint4 v = *(const uint4*)&d_WH[(size_t)(kt + br + p * 16) * 512 + nblk + bco];
            *(uint4*)&Bs[br + p * 16][bco] = v;
        }
        __syncthreads();

#pragma unroll
        for (int ks = 0; ks < GBK; ks += 16) {
            uint32_t a[2][4];
#pragma unroll
            for (int mt = 0; mt < 2; ++mt) {
                uint32_t ad = smem_u32(&As[wm0 + mt * 16 + (lane & 15)][ks + (lane >> 4) * 8]);
                LDMATRIX_X4(a[mt][0], a[mt][1], a[mt][2], a[mt][3], ad);
            }
#pragma unroll
            for (int np = 0; np < 4; ++np) {
                uint32_t bd = smem_u32(&Bs[ks + (lane & 15)][wn0 + np * 16 + (lane >> 4) * 8]);
                uint32_t b0, b1, b2, b3;
                LDMATRIX_X4_T(b0, b1, b2, b3, bd);
#pragma unroll
                for (int mt = 0; mt < 2; ++mt) {
                    MMA16816(c[mt][2 * np],     a[mt], b0, b1);
                    MMA16816(c[mt][2 * np + 1], a[mt], b2, b3);
                }
            }
        }
        __syncthreads();
    }

    // epilogue
    bool is_hs = (nblk < HID_ALL);
    int coff = is_hs ? nblk : (nblk - HID_ALL);
#pragma unroll
    for (int mt = 0; mt < 2; ++mt) {
        int row0 = mblk + wm0 + mt * 16 + (lane >> 2);
        int row1 = row0 + 8;
#pragma unroll
        for (int nt = 0; nt < 8; ++nt) {
            int col = wn0 + nt * 8 + (lane & 3) * 2;
            float bv0 = sBias[col], bv1 = sBias[col + 1];
            float v00 = c[mt][nt][0] + bv0, v01 = c[mt][nt][1] + bv1;
            float v10 = c[mt][nt][2] + bv0, v11 = c[mt][nt][3] + bv1;
            if (is_hs) {
                if (row0 < N_NODES) {
                    __half2 h = __floats2half2_rn(v00, v01);
                    *(__half2*)&d_hs_h[(size_t)row0 * HID_ALL + coff + col] = h;
                }
                if (row1 < N_NODES) {
                    __half2 h = __floats2half2_rn(v10, v11);
                    *(__half2*)&d_hs_h[(size_t)row1 * HID_ALL + coff + col] = h;
                }
            } else {
                if (row0 < N_NODES)
                    *(float2*)&d_hd[(size_t)row0 * HID_ALL + coff + col] = make_float2(v00, v01);
                if (row1 < N_NODES)
                    *(float2*)&d_hd[(size_t)row1 * HID_ALL + coff + col] = make_float2(v10, v11);
            }
        }
    }
}

// ---------------- Layer-1 fused edge softmax+aggregate + ELU + layer-2 projection ----------------
__device__ __forceinline__ float lrelu(float x) { return fmaxf(x, 0.2f * x); }

__global__ void __launch_bounds__(256) edge1_kernel(
    const float* __restrict__ attn1,
    const float* __restrict__ W2s, const float* __restrict__ b2s,
    const float* __restrict__ W2d, const float* __restrict__ b2d)
{
    __shared__ __align__(16) float sW[4][HID_ALL];
    int tid = threadIdx.x;
    sW[0][tid] = W2s[2 * tid + 0];
    sW[1][tid] = W2s[2 * tid + 1];
    sW[2][tid] = W2d[2 * tid + 0];
    sW[3][tid] = W2d[2 * tid + 1];
    __syncthreads();

    int warp = tid >> 5, lane = tid & 31;
    int node = blockIdx.x * 8 + warp;
    if (node >= N_NODES) return;

    const float* hdp = &d_hd[(size_t)node * HID_ALL + lane * 8];
    float4 hd0 = *(const float4*)hdp;
    float4 hd1 = *(const float4*)(hdp + 4);
    float4 at0 = *(const float4*)&attn1[lane * 8];
    float4 at1 = *(const float4*)&attn1[lane * 8 + 4];

    float acc0 = 0.f, acc1 = 0.f, acc2 = 0.f, acc3 = 0.f;
    float acc4 = 0.f, acc5 = 0.f, acc6 = 0.f, acc7 = 0.f;
    float denom = 0.f;

    int e0 = d_rowptr[node], e1 = d_rowptr[node + 1];
    int s = (e0 < e1) ? d_srcsorted[e0] : 0;
    for (int e = e0; e < e1; ++e) {
        int snext = (e + 1 < e1) ? d_srcsorted[e + 1] : 0;
        uint4 raw = *(const uint4*)&d_hs_h[(size_t)s * HID_ALL + lane * 8];
        float2 f0 = __half22float2(*(__half2*)&raw.x);
        float2 f1 = __half22float2(*(__half2*)&raw.y);
        float2 f2 = __half22float2(*(__half2*)&raw.z);
        float2 f3 = __half22float2(*(__half2*)&raw.w);

        float sc = 0.f;
        sc = fmaf(lrelu(f0.x + hd0.x), at0.x, sc);
        sc = fmaf(lrelu(f0.y + hd0.y), at0.y, sc);
        sc = fmaf(lrelu(f1.x + hd0.z), at0.z, sc);
        sc = fmaf(lrelu(f1.y + hd0.w), at0.w, sc);
        sc = fmaf(lrelu(f2.x + hd1.x), at1.x, sc);
        sc = fmaf(lrelu(f2.y + hd1.y), at1.y, sc);
        sc = fmaf(lrelu(f3.x + hd1.z), at1.z, sc);
        sc = fmaf(lrelu(f3.y + hd1.w), at1.w, sc);
        sc += __shfl_xor_sync(0xffffffffu, sc, 1, 8);
        sc += __shfl_xor_sync(0xffffffffu, sc, 2, 8);
        sc += __shfl_xor_sync(0xffffffffu, sc, 4, 8);

        float ex = __expf(sc);
        denom += ex;
        acc0 = fmaf(ex, f0.x, acc0);
        acc1 = fmaf(ex, f0.y, acc1);
        acc2 = fmaf(ex, f1.x, acc2);
        acc3 = fmaf(ex, f1.y, acc3);
        acc4 = fmaf(ex, f2.x, acc4);
        acc5 = fmaf(ex, f2.y, acc5);
        acc6 = fmaf(ex, f3.x, acc6);
        acc7 = fmaf(ex, f3.y, acc7);
        s = snext;
    }

    float inv = (denom > 0.f) ? (1.f / denom) : 0.f;
    float h[8];
    h[0] = acc0 * inv; h[1] = acc1 * inv; h[2] = acc2 * inv; h[3] = acc3 * inv;
    h[4] = acc4 * inv; h[5] = acc5 * inv; h[6] = acc6 * inv; h[7] = acc7 * inv;
#pragma unroll
    for (int j = 0; j < 8; ++j)
        h[j] = (h[j] > 0.f) ? h[j] : expm1f(h[j]);

    float p[4];
#pragma unroll
    for (int cdx = 0; cdx < 4; ++cdx) {
        float4 wa = *(const float4*)&sW[cdx][lane * 8];
        float4 wb = *(const float4*)&sW[cdx][lane * 8 + 4];
        p[cdx] = h[0] * wa.x + h[1] * wa.y + h[2] * wa.z + h[3] * wa.w
               + h[4] * wb.x + h[5] * wb.y + h[6] * wb.z + h[7] * wb.w;
    }
#pragma unroll
    for (int o = 16; o > 0; o >>= 1) {
        p[0] += __shfl_xor_sync(0xffffffffu, p[0], o);
        p[1] += __shfl_xor_sync(0xffffffffu, p[1], o);
        p[2] += __shfl_xor_sync(0xffffffffu, p[2], o);
        p[3] += __shfl_xor_sync(0xffffffffu, p[3], o);
    }
    if (lane == 0) {
        d_hs2[node * 2 + 0] = p[0] + b2s[0];
        d_hs2[node * 2 + 1] = p[1] + b2s[1];
        d_hd2[node * 2 + 0] = p[2] + b2d[0];
        d_hd2[node * 2 + 1] = p[3] + b2d[1];
    }
}

// ---------------- Layer-2 edge softmax+aggregate ----------------
__global__ void __launch_bounds__(256) edge2_kernel(
    const float* __restrict__ attn2, float* __restrict__ out)
{
    int tid = threadIdx.x;
    int warp = tid >> 5, lane = tid & 31;
    int node = blockIdx.x * 8 + warp;
    if (node >= N_NODES) return;

    float a0 = attn2[0], a1 = attn2[1];
    float2 hdv = *(const float2*)&d_hd2[node * 2];
    int e0 = d_rowptr[node], e1 = d_rowptr[node + 1];

    float acc0 = 0.f, acc1 = 0.f, den = 0.f;
    for (int e = e0 + lane; e < e1; e += 32) {
        int s = d_srcsorted[e];
        float2 sv = *(const float2*)&d_hs2[2 * s];
        float t0 = lrelu(sv.x + hdv.x);
        float t1 = lrelu(sv.y + hdv.y);
        float ex = __expf(fmaf(t0, a0, t1 * a1));
        den += ex;
        acc0 = fmaf(ex, sv.x, acc0);
        acc1 = fmaf(ex, sv.y, acc1);
    }
#pragma unroll
    for (int o = 16; o > 0; o >>= 1) {
        acc0 += __shfl_xor_sync(0xffffffffu, acc0, o);
        acc1 += __shfl_xor_sync(0xffffffffu, acc1, o);
        den  += __shfl_xor_sync(0xffffffffu, den, o);
    }
    if (lane == 0) {
        float inv = (den > 0.f) ? (1.f / den) : 0.f;
        out[node * 2 + 0] = acc0 * inv;
        out[node * 2 + 1] = acc1 * inv;
    }
}

// ---------------- launch ----------------
extern "C" void kernel_launch(void* const* d_in, const int* in_sizes, int n_in,
                              void* d_out, int out_size)
{
    const float* feat  = (const float*)d_in[0];
    const int*   src   = (const int*)d_in[1];
    const int*   dst   = (const int*)d_in[2];
    const float* W1s   = (const float*)d_in[3];
    const float* b1s   = (const float*)d_in[4];
    const float* W1d   = (const float*)d_in[5];
    const float* b1d   = (const float*)d_in[6];
    const float* attn1 = (const float*)d_in[7];
    const float* W2s   = (const float*)d_in[8];
    const float* b2s   = (const float*)d_in[9];
    const float* W2d   = (const float*)d_in[10];
    const float* b2d   = (const float*)d_in[11];
    const float* attn2 = (const float*)d_in[12];
    float* out = (float*)d_out;

    zero_cnt_kernel<<<(N_NODES + 255) / 256, 256>>>();
    hist_kernel<<<(N_EDGES + 255) / 256, 256>>>(dst);

    int conv_total = FEATV + FEAT_IN * 512 + 512;
    convert_kernel<<<(conv_total + 255) / 256, 256>>>(feat, W1s, W1d, b1s, b1d);

    scan_kernel<<<1, 1024>>>();
    scatter_kernel<<<(N_EDGES + 255) / 256, 256>>>(src, dst);

    dim3 gg((N_NODES + GBM - 1) / GBM, 4);
    gemm_mma_kernel<<<gg, 256>>>();

    edge1_kernel<<<(N_NODES + 7) / 8, 256>>>(attn1, W2s, b2s, W2d, b2d);
    edge2_kernel<<<(N_NODES + 7) / 8, 256>>>(attn2, out);
}